// round 8
// baseline (speedup 1.0000x reference)
#include <cuda_runtime.h>
#include <math.h>

#define H 4096
#define GRID 256
#define THREADS 512
#define RPB 16           // rows per block (one per warp)
#define NMAX 16
#define THRESH 0.99f     // 1 - EPS

#define CK 256           // chunk: floats per row per stage
#define NCHUNK (H / CK)  // 16
#define DEPTH 2          // pipeline depth

// dynamic smem layout (floats): X[4096] | S[4096] | bufI[DEPTH*RPB*CK] | bufH[DEPTH*RPB*CK]
#define SMEM_FLOATS (2 * H + 2 * DEPTH * RPB * CK)

// ---- scratch (no allocations allowed) ----
__device__ float g_u0[H];          // W_ih@x0 + b_ih + b_hh (steps t>=1)
__device__ float g_sbuf[2][H];     // ping-pong hidden state
__device__ float g_hpart[2][GRID]; // per-block halt-dot partials (ping-pong)
__device__ unsigned g_barcount = 0;
__device__ unsigned g_bargen = 0;

// 256-bit pinned load: L2::evict_last (W_out stays resident across graph replays)
__device__ __forceinline__ void ldg256_keep(const float* __restrict__ p, float v[8]) {
    unsigned r0, r1, r2, r3, r4, r5, r6, r7;
    asm volatile("ld.global.nc.L2::evict_last.v8.b32 {%0,%1,%2,%3,%4,%5,%6,%7}, [%8];"
                 : "=r"(r0), "=r"(r1), "=r"(r2), "=r"(r3),
                   "=r"(r4), "=r"(r5), "=r"(r6), "=r"(r7)
                 : "l"(p));
    v[0] = __uint_as_float(r0); v[1] = __uint_as_float(r1);
    v[2] = __uint_as_float(r2); v[3] = __uint_as_float(r3);
    v[4] = __uint_as_float(r4); v[5] = __uint_as_float(r5);
    v[6] = __uint_as_float(r6); v[7] = __uint_as_float(r7);
}

// cp.async 16B with an L2 cache-hint policy
__device__ __forceinline__ void cp16(unsigned smem_addr, const float* __restrict__ g,
                                     unsigned long long pol) {
    asm volatile("cp.async.cg.shared.global.L2::cache_hint [%0], [%1], 16, %2;"
                 :: "r"(smem_addr), "l"(g), "l"(pol) : "memory");
}
__device__ __forceinline__ void cp_commit() {
    asm volatile("cp.async.commit_group;" ::: "memory");
}
template <int N>
__device__ __forceinline__ void cp_wait() {
    asm volatile("cp.async.wait_group %0;" :: "n"(N) : "memory");
}

// grid-wide barrier (all GRID blocks co-resident: 2 CTA/SM x 148 SM = 296 >= 256)
__device__ __forceinline__ void gbar() {
    __syncthreads();
    if (threadIdx.x == 0) {
        __threadfence();
        unsigned gen = *(volatile unsigned*)&g_bargen;
        if (atomicAdd(&g_barcount, 1u) == GRID - 1u) {
            g_barcount = 0u;
            __threadfence();
            atomicExch(&g_bargen, gen + 1u);
        } else {
            while (*(volatile unsigned*)&g_bargen == gen) { }
            __threadfence();
        }
    }
    __syncthreads();
}

// single-stream warp dot, evict-first LDG.128 (rare t>=1 path); result in ALL lanes
__device__ __forceinline__ float warpdot8(const float* __restrict__ w,
                                          const float4* __restrict__ sv) {
    const float4* wr = (const float4*)w;
    const int lane = threadIdx.x & 31;
    float acc = 0.f;
#pragma unroll 8
    for (int i = lane; i < H / 4; i += 32) {
        float4 a = __ldcs(wr + i);
        float4 b = sv[i];
        acc = fmaf(a.x, b.x, acc);
        acc = fmaf(a.y, b.y, acc);
        acc = fmaf(a.z, b.z, acc);
        acc = fmaf(a.w, b.w, acc);
    }
#pragma unroll
    for (int o = 16; o > 0; o >>= 1) acc += __shfl_xor_sync(0xffffffffu, acc, o);
    return acc;
}

// pinned warp dot (W_out): 256-bit evict_last loads; result in ALL lanes
__device__ __forceinline__ float warpdot_keep(const float* __restrict__ w,
                                              const float4* __restrict__ sv) {
    const int lane = threadIdx.x & 31;
    float acc = 0.f;
#pragma unroll 4
    for (int i = lane; i < H / 8; i += 32) {
        float a[8];
        ldg256_keep(w + (size_t)i * 8, a);
        float4 b0 = sv[2 * i];
        float4 b1 = sv[2 * i + 1];
        acc = fmaf(a[0], b0.x, acc);
        acc = fmaf(a[1], b0.y, acc);
        acc = fmaf(a[2], b0.z, acc);
        acc = fmaf(a[3], b0.w, acc);
        acc = fmaf(a[4], b1.x, acc);
        acc = fmaf(a[5], b1.y, acc);
        acc = fmaf(a[6], b1.z, acc);
        acc = fmaf(a[7], b1.w, acc);
    }
#pragma unroll
    for (int o = 16; o > 0; o >>= 1) acc += __shfl_xor_sync(0xffffffffu, acc, o);
    return acc;
}

__global__ void __launch_bounds__(THREADS, 2) skiparnn_kernel(
    const float* __restrict__ x,     const float* __restrict__ s0,
    const float* __restrict__ y0,    const float* __restrict__ h0,
    const float* __restrict__ W_ih,  const float* __restrict__ b_ih,
    const float* __restrict__ W_hh,  const float* __restrict__ b_hh,
    const float* __restrict__ W_halt,const float* __restrict__ b_halt,
    const float* __restrict__ W_out, const float* __restrict__ b_out,
    float* __restrict__ out)
{
    extern __shared__ __align__(16) float dyn[];
    float* smemX = dyn;                 // [H]
    float* smemS = dyn + H;             // [H]
    float* bufI  = dyn + 2 * H;                     // [DEPTH][RPB][CK]
    float* bufH  = dyn + 2 * H + DEPTH * RPB * CK;  // [DEPTH][RPB][CK]
    __shared__ float sh_hp[RPB];

    const int tid  = threadIdx.x;
    const int warp = tid >> 5;
    const int lane = tid & 31;
    const int bid  = blockIdx.x;
    const int r    = bid * RPB + warp;          // this warp's row (0..4095)

    const float h0v = h0[0];
    if (h0v >= THRESH) {
        int g = bid * THREADS + tid;
        if (g < H) { out[g] = y0[g]; out[H + g] = s0[g]; }
        if (g == 0) { out[2 * H] = 0.f; out[2 * H + 1] = h0v - 1.f; }
        return;
    }

    // stage x1 and s0 into shared
    for (int i = tid; i < H; i += THREADS) {
        smemX[i] = (i == 0) ? 1.f : x[i - 1];
        smemS[i] = s0[i];
    }
    __syncthreads();

    // ---- step 0: cp.async depth-2 pipelined dual matvec ----
    // W_ih: fractional evict_last (deterministic ~25% of lines pinned across replays)
    // W_hh: evict_first (pure stream)
    {
        unsigned long long polI, polH;
        asm volatile("createpolicy.fractional.L2::evict_last.b64 %0, 0.25;" : "=l"(polI));
        asm volatile("createpolicy.fractional.L2::evict_first.b64 %0, 1.0;" : "=l"(polH));

        const float* wi = W_ih + (size_t)r * H;
        const float* wh = W_hh + (size_t)r * H;
        unsigned bI = (unsigned)__cvta_generic_to_shared(bufI + warp * CK);
        unsigned bH = (unsigned)__cvta_generic_to_shared(bufH + warp * CK);
        const unsigned slotStride = RPB * CK * 4u;   // bytes per slot

        // prologue: issue stages 0..DEPTH-1
#pragma unroll
        for (int c = 0; c < DEPTH; c++) {
            int slot = c;
#pragma unroll
            for (int k = 0; k < CK / 128; k++) {
                int j = k * 32 + lane;
                cp16(bI + slot * slotStride + j * 16u, wi + c * CK + j * 4, polI);
                cp16(bH + slot * slotStride + j * 16u, wh + c * CK + j * 4, polH);
            }
            cp_commit();
        }

        float accI = 0.f, accH = 0.f;
        const float4* sx4 = (const float4*)smemX;
        const float4* ss4 = (const float4*)smemS;
        const float4* bI4 = (const float4*)(bufI + warp * CK);
        const float4* bH4 = (const float4*)(bufH + warp * CK);
        const int slotStride4 = RPB * CK / 4;      // float4 per slot

        for (int c = 0; c < NCHUNK; c++) {
            cp_wait<DEPTH - 1>();                  // stage c complete (per-thread)
            int slot = c % DEPTH;
#pragma unroll
            for (int k = 0; k < CK / 128; k++) {
                int j = k * 32 + lane;             // float4 index within chunk
                float4 a  = bI4[slot * slotStride4 + j];
                float4 b  = bH4[slot * slotStride4 + j];
                float4 xv = sx4[c * (CK / 4) + j];
                float4 sv = ss4[c * (CK / 4) + j];
                accI = fmaf(a.x, xv.x, accI);
                accI = fmaf(a.y, xv.y, accI);
                accI = fmaf(a.z, xv.z, accI);
                accI = fmaf(a.w, xv.w, accI);
                accH = fmaf(b.x, sv.x, accH);
                accH = fmaf(b.y, sv.y, accH);
                accH = fmaf(b.z, sv.z, accH);
                accH = fmaf(b.w, sv.w, accH);
            }
            int cn = c + DEPTH;
            if (cn < NCHUNK) {
                int ns = cn % DEPTH;
#pragma unroll
                for (int k = 0; k < CK / 128; k++) {
                    int j = k * 32 + lane;
                    cp16(bI + ns * slotStride + j * 16u, wi + cn * CK + j * 4, polI);
                    cp16(bH + ns * slotStride + j * 16u, wh + cn * CK + j * 4, polH);
                }
            }
            cp_commit();                           // keep group count advancing
        }
        cp_wait<0>();

#pragma unroll
        for (int o = 16; o > 0; o >>= 1) {
            accI += __shfl_xor_sync(0xffffffffu, accI, o);
            accH += __shfl_xor_sync(0xffffffffu, accH, o);
        }
        float bias = b_ih[r] + b_hh[r];
        float snew = tanhf(accI + bias + accH);
        if (lane == 0) {
            // W_ih@x0 = W_ih@x1 - W_ih[:,0]
            g_u0[r]      = accI - __ldg(W_ih + (size_t)r * H) + bias;
            g_sbuf[0][r] = snew;
            sh_hp[warp]  = snew * __ldg(W_halt + r);
        }
    }
    __syncthreads();
    if (tid == 0) {
        float hp = 0.f;
#pragma unroll
        for (int i = 0; i < RPB; i++) hp += sh_hp[i];
        g_hpart[0][bid] = hp;
    }
    gbar();

    float acc    = h0v;
    float ponder = 0.f;
    const float bh = b_halt[0];
    int   t = 0;
    int   haltstep = -1;
    float lastacc  = 0.f;

    while (true) {
        // deterministic fixed-order reduction of halt-dot partials (same in all blocks)
        float hd;
        {
            const float* hp = g_hpart[t & 1];
            float a = 0.f;
#pragma unroll
            for (int i = lane; i < GRID; i += 32) a += hp[i];
#pragma unroll
            for (int o = 16; o > 0; o >>= 1) a += __shfl_xor_sync(0xffffffffu, a, o);
            hd = a;
        }
        float accNew = acc + 2.f / (1.f + expf(-(hd + bh)));
        if (accNew >= THRESH) { haltstep = t; lastacc = accNew; break; }
        ponder += 1.f;
        acc = accNew;
        if (t == NMAX - 1) break;

        // ---- step t+1: z = u0 + W_hh @ s (streamed; rare path) ----
        for (int i = tid; i < H; i += THREADS) smemS[i] = g_sbuf[t & 1][i];
        __syncthreads();
        float z    = g_u0[r] + warpdot8(W_hh + (size_t)r * H, (const float4*)smemS);
        float snew = tanhf(z);
        if (lane == 0) {
            g_sbuf[(t + 1) & 1][r] = snew;
            sh_hp[warp]            = snew * __ldg(W_halt + r);
        }
        __syncthreads();
        if (tid == 0) {
            float hp = 0.f;
#pragma unroll
            for (int i = 0; i < RPB; i++) hp += sh_hp[i];
            g_hpart[(t + 1) & 1][bid] = hp;
        }
        t++;
        gbar();
    }

    if (haltstep >= 0) {
        // y = W_out @ s_halt + b_out ; s = s_halt  (W_out pinned in L2 via evict_last)
        for (int i = tid; i < H; i += THREADS) smemS[i] = g_sbuf[haltstep & 1][i];
        __syncthreads();
        float yv = warpdot_keep(W_out + (size_t)r * H, (const float4*)smemS) + b_out[r];
        if (lane == 0) {
            out[r]     = yv;
            out[H + r] = smemS[r];
        }
        if (bid == 0 && tid == 0) {
            out[2 * H]     = ponder;           // = haltstep = n-1
            out[2 * H + 1] = lastacc - 1.f;
        }
    } else {
        // never halted within 16 steps: halt_bin all zero
        int g = bid * THREADS + tid;
        if (g < H) { out[g] = 0.f; out[H + g] = 0.f; }
        if (g == 0) { out[2 * H] = ponder; out[2 * H + 1] = -1.f; }
    }
}

extern "C" void kernel_launch(void* const* d_in, const int* in_sizes, int n_in,
                              void* d_out, int out_size) {
    (void)in_sizes; (void)n_in; (void)out_size;
    // idempotent attribute set (not an allocation; safe pre-capture and in capture)
    cudaFuncSetAttribute(skiparnn_kernel,
                         cudaFuncAttributeMaxDynamicSharedMemorySize,
                         SMEM_FLOATS * (int)sizeof(float));
    skiparnn_kernel<<<GRID, THREADS, SMEM_FLOATS * sizeof(float)>>>(
        (const float*)d_in[0],  (const float*)d_in[1],
        (const float*)d_in[2],  (const float*)d_in[3],
        (const float*)d_in[4],  (const float*)d_in[5],
        (const float*)d_in[6],  (const float*)d_in[7],
        (const float*)d_in[8],  (const float*)d_in[9],
        (const float*)d_in[10], (const float*)d_in[11],
        (float*)d_out);
}

// round 9
// speedup vs baseline: 1.0530x; 1.0530x over previous
#include <cuda_runtime.h>
#include <math.h>

#define H 4096
#define GRID 256
#define THREADS 512
#define RPB 16           // rows per block (one per warp)
#define NMAX 16
#define THRESH 0.99f     // 1 - EPS
#define DEPTH 2          // TMA pipeline depth (row-pair stages)

// dynamic smem (floats): X[H] | S[H] | bufI[DEPTH*H rows? no: DEPTH rows] | bufH[DEPTH rows]
// bufI/bufH: DEPTH slots of one full row (4096 floats) each
#define SMEM_FLOATS (2 * H + 2 * DEPTH * H)

// ---- scratch (no allocations allowed) ----
__device__ float g_u0[H];          // W_ih@x0 + b_ih + b_hh (steps t>=1)
__device__ float g_sbuf[2][H];     // ping-pong hidden state
__device__ float g_hpart[2][GRID]; // per-block halt-dot partials (ping-pong)
__device__ unsigned g_barcount = 0;
__device__ unsigned g_bargen = 0;

// 256-bit pinned load: L2::evict_last (W_out stays resident across graph replays)
__device__ __forceinline__ void ldg256_keep(const float* __restrict__ p, float v[8]) {
    unsigned r0, r1, r2, r3, r4, r5, r6, r7;
    asm volatile("ld.global.nc.L2::evict_last.v8.b32 {%0,%1,%2,%3,%4,%5,%6,%7}, [%8];"
                 : "=r"(r0), "=r"(r1), "=r"(r2), "=r"(r3),
                   "=r"(r4), "=r"(r5), "=r"(r6), "=r"(r7)
                 : "l"(p));
    v[0] = __uint_as_float(r0); v[1] = __uint_as_float(r1);
    v[2] = __uint_as_float(r2); v[3] = __uint_as_float(r3);
    v[4] = __uint_as_float(r4); v[5] = __uint_as_float(r5);
    v[6] = __uint_as_float(r6); v[7] = __uint_as_float(r7);
}

// ---- TMA bulk + mbarrier helpers ----
__device__ __forceinline__ void tma_bulk(unsigned dst, const float* __restrict__ src,
                                         unsigned bytes, unsigned mbar,
                                         unsigned long long pol) {
    asm volatile("cp.async.bulk.shared::cta.global.mbarrier::complete_tx::bytes.L2::cache_hint"
                 " [%0], [%1], %2, [%3], %4;"
                 :: "r"(dst), "l"(src), "r"(bytes), "r"(mbar), "l"(pol) : "memory");
}
__device__ __forceinline__ void mbar_init(unsigned addr, unsigned count) {
    asm volatile("mbarrier.init.shared.b64 [%0], %1;" :: "r"(addr), "r"(count) : "memory");
}
__device__ __forceinline__ void mbar_expect_tx(unsigned addr, unsigned tx) {
    asm volatile("mbarrier.arrive.expect_tx.shared.b64 _, [%0], %1;"
                 :: "r"(addr), "r"(tx) : "memory");
}
__device__ __forceinline__ void mbar_wait(unsigned addr, unsigned parity) {
    unsigned done = 0;
    while (!done) {
        asm volatile("{\n\t.reg .pred p;\n\t"
                     "mbarrier.try_wait.parity.shared.b64 p, [%1], %2;\n\t"
                     "selp.b32 %0, 1, 0, p;\n\t}"
                     : "=r"(done) : "r"(addr), "r"(parity) : "memory");
    }
}
__device__ __forceinline__ void fence_async() {
    asm volatile("fence.proxy.async.shared::cta;" ::: "memory");
}

// grid-wide barrier (all GRID blocks co-resident: 2 CTA/SM x 148 SM = 296 >= 256)
__device__ __forceinline__ void gbar() {
    __syncthreads();
    if (threadIdx.x == 0) {
        __threadfence();
        unsigned gen = *(volatile unsigned*)&g_bargen;
        if (atomicAdd(&g_barcount, 1u) == GRID - 1u) {
            g_barcount = 0u;
            __threadfence();
            atomicExch(&g_bargen, gen + 1u);
        } else {
            while (*(volatile unsigned*)&g_bargen == gen) { }
            __threadfence();
        }
    }
    __syncthreads();
}

// single-stream warp dot, evict-first LDG.128 (rare t>=1 path); result in ALL lanes
__device__ __forceinline__ float warpdot8(const float* __restrict__ w,
                                          const float4* __restrict__ sv) {
    const float4* wr = (const float4*)w;
    const int lane = threadIdx.x & 31;
    float acc = 0.f;
#pragma unroll 8
    for (int i = lane; i < H / 4; i += 32) {
        float4 a = __ldcs(wr + i);
        float4 b = sv[i];
        acc = fmaf(a.x, b.x, acc);
        acc = fmaf(a.y, b.y, acc);
        acc = fmaf(a.z, b.z, acc);
        acc = fmaf(a.w, b.w, acc);
    }
#pragma unroll
    for (int o = 16; o > 0; o >>= 1) acc += __shfl_xor_sync(0xffffffffu, acc, o);
    return acc;
}

// pinned warp dot (W_out): 256-bit evict_last loads; result in ALL lanes
__device__ __forceinline__ float warpdot_keep(const float* __restrict__ w,
                                              const float4* __restrict__ sv) {
    const int lane = threadIdx.x & 31;
    float acc = 0.f;
#pragma unroll 4
    for (int i = lane; i < H / 8; i += 32) {
        float a[8];
        ldg256_keep(w + (size_t)i * 8, a);
        float4 b0 = sv[2 * i];
        float4 b1 = sv[2 * i + 1];
        acc = fmaf(a[0], b0.x, acc);
        acc = fmaf(a[1], b0.y, acc);
        acc = fmaf(a[2], b0.z, acc);
        acc = fmaf(a[3], b0.w, acc);
        acc = fmaf(a[4], b1.x, acc);
        acc = fmaf(a[5], b1.y, acc);
        acc = fmaf(a[6], b1.z, acc);
        acc = fmaf(a[7], b1.w, acc);
    }
#pragma unroll
    for (int o = 16; o > 0; o >>= 1) acc += __shfl_xor_sync(0xffffffffu, acc, o);
    return acc;
}

__global__ void __launch_bounds__(THREADS, 2) skiparnn_kernel(
    const float* __restrict__ x,     const float* __restrict__ s0,
    const float* __restrict__ y0,    const float* __restrict__ h0,
    const float* __restrict__ W_ih,  const float* __restrict__ b_ih,
    const float* __restrict__ W_hh,  const float* __restrict__ b_hh,
    const float* __restrict__ W_halt,const float* __restrict__ b_halt,
    const float* __restrict__ W_out, const float* __restrict__ b_out,
    float* __restrict__ out)
{
    extern __shared__ __align__(16) float dyn[];
    float* smemX = dyn;                    // [H]
    float* smemS = dyn + H;                // [H]
    float* bufI  = dyn + 2 * H;            // [DEPTH][H]
    float* bufH  = dyn + 2 * H + DEPTH * H;// [DEPTH][H]
    __shared__ float pI[RPB][RPB];         // per-stage per-warp partials (W_ih)
    __shared__ float pH[RPB][RPB];         // per-stage per-warp partials (W_hh)
    __shared__ float sh_hp[RPB];
    __shared__ __align__(8) unsigned long long mbars[DEPTH];

    const int tid  = threadIdx.x;
    const int warp = tid >> 5;
    const int lane = tid & 31;
    const int bid  = blockIdx.x;
    const int r    = bid * RPB + warp;          // this warp's row (0..4095)

    const float h0v = h0[0];
    if (h0v >= THRESH) {
        int g = bid * THREADS + tid;
        if (g < H) { out[g] = y0[g]; out[H + g] = s0[g]; }
        if (g == 0) { out[2 * H] = 0.f; out[2 * H + 1] = h0v - 1.f; }
        return;
    }

    // stage x1 and s0 into shared
    for (int i = tid; i < H; i += THREADS) {
        smemX[i] = (i == 0) ? 1.f : x[i - 1];
        smemS[i] = s0[i];
    }
    unsigned mb[DEPTH];
#pragma unroll
    for (int d = 0; d < DEPTH; d++)
        mb[d] = (unsigned)__cvta_generic_to_shared(&mbars[d]);
    if (tid == 0) {
        mbar_init(mb[0], 1);
        mbar_init(mb[1], 1);
    }
    __syncthreads();   // X/S staged + mbarriers initialized

    // ---- step 0: TMA-bulk pipelined dual matvec (rows streamed whole) ----
    {
        unsigned long long pol;
        asm volatile("createpolicy.fractional.L2::evict_first.b64 %0, 1.0;" : "=l"(pol));

        const float* wiB = W_ih + (size_t)bid * RPB * H;   // CTA's contiguous 256KB block
        const float* whB = W_hh + (size_t)bid * RPB * H;
        unsigned bI0 = (unsigned)__cvta_generic_to_shared(bufI);
        unsigned bH0 = (unsigned)__cvta_generic_to_shared(bufH);
        const unsigned rowBytes = H * 4u;

        if (tid == 0) {
            fence_async();
#pragma unroll
            for (int w = 0; w < DEPTH; w++) {
                mbar_expect_tx(mb[w], 2 * rowBytes);
                tma_bulk(bI0 + w * rowBytes, wiB + (size_t)w * H, rowBytes, mb[w], pol);
                tma_bulk(bH0 + w * rowBytes, whB + (size_t)w * H, rowBytes, mb[w], pol);
            }
        }

        const float4* sx4 = (const float4*)smemX;
        const float4* ss4 = (const float4*)smemS;
        const float4* bI4 = (const float4*)bufI;
        const float4* bH4 = (const float4*)bufH;
        const int slotF4 = H / 4;                        // float4 per slot

        for (int w = 0; w < RPB; w++) {
            int slot = w & 1;
            int par  = (w >> 1) & 1;
            mbar_wait(mb[slot], par);

            // whole block dots row w of I (vs x) and row w of H (vs s)
            float4 a0 = bI4[slot * slotF4 + 2 * tid];
            float4 a1 = bI4[slot * slotF4 + 2 * tid + 1];
            float4 c0 = bH4[slot * slotF4 + 2 * tid];
            float4 c1 = bH4[slot * slotF4 + 2 * tid + 1];
            float4 x0 = sx4[2 * tid], x1 = sx4[2 * tid + 1];
            float4 v0 = ss4[2 * tid], v1 = ss4[2 * tid + 1];
            float aI = 0.f, aH = 0.f;
            aI = fmaf(a0.x, x0.x, aI); aI = fmaf(a0.y, x0.y, aI);
            aI = fmaf(a0.z, x0.z, aI); aI = fmaf(a0.w, x0.w, aI);
            aI = fmaf(a1.x, x1.x, aI); aI = fmaf(a1.y, x1.y, aI);
            aI = fmaf(a1.z, x1.z, aI); aI = fmaf(a1.w, x1.w, aI);
            aH = fmaf(c0.x, v0.x, aH); aH = fmaf(c0.y, v0.y, aH);
            aH = fmaf(c0.z, v0.z, aH); aH = fmaf(c0.w, v0.w, aH);
            aH = fmaf(c1.x, v1.x, aH); aH = fmaf(c1.y, v1.y, aH);
            aH = fmaf(c1.z, v1.z, aH); aH = fmaf(c1.w, v1.w, aH);
#pragma unroll
            for (int o = 16; o > 0; o >>= 1) {
                aI += __shfl_xor_sync(0xffffffffu, aI, o);
                aH += __shfl_xor_sync(0xffffffffu, aH, o);
            }
            if (lane == 0) { pI[w][warp] = aI; pH[w][warp] = aH; }

            __syncthreads();   // all reads of this slot complete before reissue
            int wn = w + DEPTH;
            if (tid == 0 && wn < RPB) {
                fence_async();
                mbar_expect_tx(mb[slot], 2 * rowBytes);
                tma_bulk(bI0 + slot * rowBytes, wiB + (size_t)wn * H, rowBytes, mb[slot], pol);
                tma_bulk(bH0 + slot * rowBytes, whB + (size_t)wn * H, rowBytes, mb[slot], pol);
            }
        }

        // final: warp w reduces its row's 16 partials (all partials visible after loop syncs)
        float vI = (lane < RPB) ? pI[warp][lane] : 0.f;
        float vH = (lane < RPB) ? pH[warp][lane] : 0.f;
#pragma unroll
        for (int o = 16; o > 0; o >>= 1) {
            vI += __shfl_xor_sync(0xffffffffu, vI, o);
            vH += __shfl_xor_sync(0xffffffffu, vH, o);
        }
        float bias = b_ih[r] + b_hh[r];
        float snew = tanhf(vI + bias + vH);
        if (lane == 0) {
            // W_ih@x0 = W_ih@x1 - W_ih[:,0]
            g_u0[r]      = vI - __ldg(W_ih + (size_t)r * H) + bias;
            g_sbuf[0][r] = snew;
            sh_hp[warp]  = snew * __ldg(W_halt + r);
        }
    }
    __syncthreads();
    if (tid == 0) {
        float hp = 0.f;
#pragma unroll
        for (int i = 0; i < RPB; i++) hp += sh_hp[i];
        g_hpart[0][bid] = hp;
    }
    gbar();

    float acc    = h0v;
    float ponder = 0.f;
    const float bh = b_halt[0];
    int   t = 0;
    int   haltstep = -1;
    float lastacc  = 0.f;

    while (true) {
        // deterministic fixed-order reduction of halt-dot partials (same in all blocks)
        float hd;
        {
            const float* hp = g_hpart[t & 1];
            float a = 0.f;
#pragma unroll
            for (int i = lane; i < GRID; i += 32) a += hp[i];
#pragma unroll
            for (int o = 16; o > 0; o >>= 1) a += __shfl_xor_sync(0xffffffffu, a, o);
            hd = a;
        }
        float accNew = acc + 2.f / (1.f + expf(-(hd + bh)));
        if (accNew >= THRESH) { haltstep = t; lastacc = accNew; break; }
        ponder += 1.f;
        acc = accNew;
        if (t == NMAX - 1) break;

        // ---- step t+1: z = u0 + W_hh @ s (streamed; rare path) ----
        for (int i = tid; i < H; i += THREADS) smemS[i] = g_sbuf[t & 1][i];
        __syncthreads();
        float z    = g_u0[r] + warpdot8(W_hh + (size_t)r * H, (const float4*)smemS);
        float snew = tanhf(z);
        if (lane == 0) {
            g_sbuf[(t + 1) & 1][r] = snew;
            sh_hp[warp]            = snew * __ldg(W_halt + r);
        }
        __syncthreads();
        if (tid == 0) {
            float hp = 0.f;
#pragma unroll
            for (int i = 0; i < RPB; i++) hp += sh_hp[i];
            g_hpart[(t + 1) & 1][bid] = hp;
        }
        t++;
        gbar();
    }

    if (haltstep >= 0) {
        // y = W_out @ s_halt + b_out ; s = s_halt  (W_out pinned in L2 via evict_last)
        for (int i = tid; i < H; i += THREADS) smemS[i] = g_sbuf[haltstep & 1][i];
        __syncthreads();
        float yv = warpdot_keep(W_out + (size_t)r * H, (const float4*)smemS) + b_out[r];
        if (lane == 0) {
            out[r]     = yv;
            out[H + r] = smemS[r];
        }
        if (bid == 0 && tid == 0) {
            out[2 * H]     = ponder;           // = haltstep = n-1
            out[2 * H + 1] = lastacc - 1.f;
        }
    } else {
        // never halted within 16 steps: halt_bin all zero
        int g = bid * THREADS + tid;
        if (g < H) { out[g] = 0.f; out[H + g] = 0.f; }
        if (g == 0) { out[2 * H] = ponder; out[2 * H + 1] = -1.f; }
    }
}

extern "C" void kernel_launch(void* const* d_in, const int* in_sizes, int n_in,
                              void* d_out, int out_size) {
    (void)in_sizes; (void)n_in; (void)out_size;
    // idempotent attribute set (not an allocation; safe pre-capture and in capture)
    cudaFuncSetAttribute(skiparnn_kernel,
                         cudaFuncAttributeMaxDynamicSharedMemorySize,
                         SMEM_FLOATS * (int)sizeof(float));
    skiparnn_kernel<<<GRID, THREADS, SMEM_FLOATS * sizeof(float)>>>(
        (const float*)d_in[0],  (const float*)d_in[1],
        (const float*)d_in[2],  (const float*)d_in[3],
        (const float*)d_in[4],  (const float*)d_in[5],
        (const float*)d_in[6],  (const float*)d_in[7],
        (const float*)d_in[8],  (const float*)d_in[9],
        (const float*)d_in[10], (const float*)d_in[11],
        (float*)d_out);
}

// round 10
// speedup vs baseline: 1.1550x; 1.0969x over previous
#include <cuda_runtime.h>
#include <math.h>

#define H 4096
#define GRID 256
#define THREADS 512
#define RPB 16           // rows per block (one per warp)
#define NMAX 16
#define THRESH 0.99f     // 1 - EPS

#define CK 256           // chunk: floats per row per stage
#define NCHUNK (H / CK)  // 16
#define DEPTH 2          // pipeline depth

#define PIN_IN_CHUNKS 5     // W_ih: first 5 of 16 chunks pinned -> 21.0 MB
#define PIN_OUT_BLKS 304    // W_out: first 304 of 512 8-float blocks pinned -> 39.8 MB
// total pinned = 60.8 MB < proven-safe ~67 MB evict_last capacity

// dynamic smem layout (floats): X[4096] | S[4096] | bufI[DEPTH*RPB*CK] | bufH[DEPTH*RPB*CK]
#define SMEM_FLOATS (2 * H + 2 * DEPTH * RPB * CK)

// ---- scratch (no allocations allowed) ----
__device__ float g_u0[H];          // W_ih@x0 + b_ih + b_hh (steps t>=1)
__device__ float g_sbuf[2][H];     // ping-pong hidden state
__device__ float g_hpart[2][GRID]; // per-block halt-dot partials (ping-pong)
__device__ unsigned g_barcount = 0;
__device__ unsigned g_bargen = 0;

// 256-bit pinned load: L2::evict_last
__device__ __forceinline__ void ldg256_keep(const float* __restrict__ p, float v[8]) {
    unsigned r0, r1, r2, r3, r4, r5, r6, r7;
    asm volatile("ld.global.nc.L2::evict_last.v8.b32 {%0,%1,%2,%3,%4,%5,%6,%7}, [%8];"
                 : "=r"(r0), "=r"(r1), "=r"(r2), "=r"(r3),
                   "=r"(r4), "=r"(r5), "=r"(r6), "=r"(r7)
                 : "l"(p));
    v[0] = __uint_as_float(r0); v[1] = __uint_as_float(r1);
    v[2] = __uint_as_float(r2); v[3] = __uint_as_float(r3);
    v[4] = __uint_as_float(r4); v[5] = __uint_as_float(r5);
    v[6] = __uint_as_float(r6); v[7] = __uint_as_float(r7);
}
// 256-bit streamed load: L2::evict_first
__device__ __forceinline__ void ldg256_stream(const float* __restrict__ p, float v[8]) {
    unsigned r0, r1, r2, r3, r4, r5, r6, r7;
    asm volatile("ld.global.nc.L2::evict_first.v8.b32 {%0,%1,%2,%3,%4,%5,%6,%7}, [%8];"
                 : "=r"(r0), "=r"(r1), "=r"(r2), "=r"(r3),
                   "=r"(r4), "=r"(r5), "=r"(r6), "=r"(r7)
                 : "l"(p));
    v[0] = __uint_as_float(r0); v[1] = __uint_as_float(r1);
    v[2] = __uint_as_float(r2); v[3] = __uint_as_float(r3);
    v[4] = __uint_as_float(r4); v[5] = __uint_as_float(r5);
    v[6] = __uint_as_float(r6); v[7] = __uint_as_float(r7);
}

// cp.async 16B with an L2 cache-hint policy
__device__ __forceinline__ void cp16(unsigned smem_addr, const float* __restrict__ g,
                                     unsigned long long pol) {
    asm volatile("cp.async.cg.shared.global.L2::cache_hint [%0], [%1], 16, %2;"
                 :: "r"(smem_addr), "l"(g), "l"(pol) : "memory");
}
__device__ __forceinline__ void cp_commit() {
    asm volatile("cp.async.commit_group;" ::: "memory");
}
template <int N>
__device__ __forceinline__ void cp_wait() {
    asm volatile("cp.async.wait_group %0;" :: "n"(N) : "memory");
}

// grid-wide barrier (all GRID blocks co-resident: 2 CTA/SM x 148 SM = 296 >= 256)
__device__ __forceinline__ void gbar() {
    __syncthreads();
    if (threadIdx.x == 0) {
        __threadfence();
        unsigned gen = *(volatile unsigned*)&g_bargen;
        if (atomicAdd(&g_barcount, 1u) == GRID - 1u) {
            g_barcount = 0u;
            __threadfence();
            atomicExch(&g_bargen, gen + 1u);
        } else {
            while (*(volatile unsigned*)&g_bargen == gen) { }
            __threadfence();
        }
    }
    __syncthreads();
}

// single-stream warp dot, evict-first LDG.128 (rare t>=1 path); result in ALL lanes
__device__ __forceinline__ float warpdot8(const float* __restrict__ w,
                                          const float4* __restrict__ sv) {
    const float4* wr = (const float4*)w;
    const int lane = threadIdx.x & 31;
    float acc = 0.f;
#pragma unroll 8
    for (int i = lane; i < H / 4; i += 32) {
        float4 a = __ldcs(wr + i);
        float4 b = sv[i];
        acc = fmaf(a.x, b.x, acc);
        acc = fmaf(a.y, b.y, acc);
        acc = fmaf(a.z, b.z, acc);
        acc = fmaf(a.w, b.w, acc);
    }
#pragma unroll
    for (int o = 16; o > 0; o >>= 1) acc += __shfl_xor_sync(0xffffffffu, acc, o);
    return acc;
}

__device__ __forceinline__ float fma8v(const float a[8], const float4* sv, int i, float acc) {
    float4 b0 = sv[2 * i];
    float4 b1 = sv[2 * i + 1];
    acc = fmaf(a[0], b0.x, acc);
    acc = fmaf(a[1], b0.y, acc);
    acc = fmaf(a[2], b0.z, acc);
    acc = fmaf(a[3], b0.w, acc);
    acc = fmaf(a[4], b1.x, acc);
    acc = fmaf(a[5], b1.y, acc);
    acc = fmaf(a[6], b1.z, acc);
    acc = fmaf(a[7], b1.w, acc);
    return acc;
}

// W_out warp dot: first PIN_OUT_BLKS blocks pinned (evict_last), rest streamed
__device__ __forceinline__ float warpdot_out(const float* __restrict__ w,
                                             const float4* __restrict__ sv) {
    const int lane = threadIdx.x & 31;
    float acc = 0.f;
#pragma unroll 4
    for (int i = lane; i < PIN_OUT_BLKS; i += 32) {
        float a[8];
        ldg256_keep(w + (size_t)i * 8, a);
        acc = fma8v(a, sv, i, acc);
    }
    // remaining blocks: indices continue the lane stride pattern
    for (int i = ((PIN_OUT_BLKS - lane + 31) / 32) * 32 + lane; i < H / 8; i += 32) {
        float a[8];
        ldg256_stream(w + (size_t)i * 8, a);
        acc = fma8v(a, sv, i, acc);
    }
#pragma unroll
    for (int o = 16; o > 0; o >>= 1) acc += __shfl_xor_sync(0xffffffffu, acc, o);
    return acc;
}

__global__ void __launch_bounds__(THREADS, 2) skiparnn_kernel(
    const float* __restrict__ x,     const float* __restrict__ s0,
    const float* __restrict__ y0,    const float* __restrict__ h0,
    const float* __restrict__ W_ih,  const float* __restrict__ b_ih,
    const float* __restrict__ W_hh,  const float* __restrict__ b_hh,
    const float* __restrict__ W_halt,const float* __restrict__ b_halt,
    const float* __restrict__ W_out, const float* __restrict__ b_out,
    float* __restrict__ out)
{
    extern __shared__ __align__(16) float dyn[];
    float* smemX = dyn;                 // [H]
    float* smemS = dyn + H;             // [H]
    float* bufI  = dyn + 2 * H;                     // [DEPTH][RPB][CK]
    float* bufH  = dyn + 2 * H + DEPTH * RPB * CK;  // [DEPTH][RPB][CK]
    __shared__ float sh_hp[RPB];

    const int tid  = threadIdx.x;
    const int warp = tid >> 5;
    const int lane = tid & 31;
    const int bid  = blockIdx.x;
    const int r    = bid * RPB + warp;          // this warp's row (0..4095)

    const float h0v = h0[0];
    if (h0v >= THRESH) {
        int g = bid * THREADS + tid;
        if (g < H) { out[g] = y0[g]; out[H + g] = s0[g]; }
        if (g == 0) { out[2 * H] = 0.f; out[2 * H + 1] = h0v - 1.f; }
        return;
    }

    // stage x1 and s0 into shared
    for (int i = tid; i < H; i += THREADS) {
        smemX[i] = (i == 0) ? 1.f : x[i - 1];
        smemS[i] = s0[i];
    }
    __syncthreads();

    // ---- step 0: cp.async depth-2 pipelined dual matvec ----
    // W_ih chunks [0, PIN_IN_CHUNKS) pinned via evict_last policy; the rest + W_hh streamed.
    {
        unsigned long long polKeep, polStream;
        asm volatile("createpolicy.fractional.L2::evict_last.b64 %0, 1.0;" : "=l"(polKeep));
        asm volatile("createpolicy.fractional.L2::evict_first.b64 %0, 1.0;" : "=l"(polStream));

        const float* wi = W_ih + (size_t)r * H;
        const float* wh = W_hh + (size_t)r * H;
        unsigned bI = (unsigned)__cvta_generic_to_shared(bufI + warp * CK);
        unsigned bH = (unsigned)__cvta_generic_to_shared(bufH + warp * CK);
        const unsigned slotStride = RPB * CK * 4u;   // bytes per slot

        // prologue: issue stages 0..DEPTH-1
#pragma unroll
        for (int c = 0; c < DEPTH; c++) {
            int slot = c;
            unsigned long long pI = (c < PIN_IN_CHUNKS) ? polKeep : polStream;
#pragma unroll
            for (int k = 0; k < CK / 128; k++) {
                int j = k * 32 + lane;
                cp16(bI + slot * slotStride + j * 16u, wi + c * CK + j * 4, pI);
                cp16(bH + slot * slotStride + j * 16u, wh + c * CK + j * 4, polStream);
            }
            cp_commit();
        }

        float accI = 0.f, accH = 0.f;
        const float4* sx4 = (const float4*)smemX;
        const float4* ss4 = (const float4*)smemS;
        const float4* bI4 = (const float4*)(bufI + warp * CK);
        const float4* bH4 = (const float4*)(bufH + warp * CK);
        const int slotStride4 = RPB * CK / 4;      // float4 per slot

        for (int c = 0; c < NCHUNK; c++) {
            cp_wait<DEPTH - 1>();                  // stage c complete (per-thread)
            int slot = c % DEPTH;
#pragma unroll
            for (int k = 0; k < CK / 128; k++) {
                int j = k * 32 + lane;             // float4 index within chunk
                float4 a  = bI4[slot * slotStride4 + j];
                float4 b  = bH4[slot * slotStride4 + j];
                float4 xv = sx4[c * (CK / 4) + j];
                float4 sv = ss4[c * (CK / 4) + j];
                accI = fmaf(a.x, xv.x, accI);
                accI = fmaf(a.y, xv.y, accI);
                accI = fmaf(a.z, xv.z, accI);
                accI = fmaf(a.w, xv.w, accI);
                accH = fmaf(b.x, sv.x, accH);
                accH = fmaf(b.y, sv.y, accH);
                accH = fmaf(b.z, sv.z, accH);
                accH = fmaf(b.w, sv.w, accH);
            }
            int cn = c + DEPTH;
            if (cn < NCHUNK) {
                int ns = cn % DEPTH;
                unsigned long long pI = (cn < PIN_IN_CHUNKS) ? polKeep : polStream;
#pragma unroll
                for (int k = 0; k < CK / 128; k++) {
                    int j = k * 32 + lane;
                    cp16(bI + ns * slotStride + j * 16u, wi + cn * CK + j * 4, pI);
                    cp16(bH + ns * slotStride + j * 16u, wh + cn * CK + j * 4, polStream);
                }
            }
            cp_commit();                           // keep group count advancing
        }
        cp_wait<0>();

#pragma unroll
        for (int o = 16; o > 0; o >>= 1) {
            accI += __shfl_xor_sync(0xffffffffu, accI, o);
            accH += __shfl_xor_sync(0xffffffffu, accH, o);
        }
        float bias = b_ih[r] + b_hh[r];
        float snew = tanhf(accI + bias + accH);
        if (lane == 0) {
            // W_ih@x0 = W_ih@x1 - W_ih[:,0]
            g_u0[r]      = accI - __ldg(W_ih + (size_t)r * H) + bias;
            g_sbuf[0][r] = snew;
            sh_hp[warp]  = snew * __ldg(W_halt + r);
        }
    }
    __syncthreads();
    if (tid == 0) {
        float hp = 0.f;
#pragma unroll
        for (int i = 0; i < RPB; i++) hp += sh_hp[i];
        g_hpart[0][bid] = hp;
    }
    gbar();

    float acc    = h0v;
    float ponder = 0.f;
    const float bh = b_halt[0];
    int   t = 0;
    int   haltstep = -1;
    float lastacc  = 0.f;

    while (true) {
        // deterministic fixed-order reduction of halt-dot partials (same in all blocks)
        float hd;
        {
            const float* hp = g_hpart[t & 1];
            float a = 0.f;
#pragma unroll
            for (int i = lane; i < GRID; i += 32) a += hp[i];
#pragma unroll
            for (int o = 16; o > 0; o >>= 1) a += __shfl_xor_sync(0xffffffffu, a, o);
            hd = a;
        }
        float accNew = acc + 2.f / (1.f + expf(-(hd + bh)));
        if (accNew >= THRESH) { haltstep = t; lastacc = accNew; break; }
        ponder += 1.f;
        acc = accNew;
        if (t == NMAX - 1) break;

        // ---- step t+1: z = u0 + W_hh @ s (streamed; rare path) ----
        for (int i = tid; i < H; i += THREADS) smemS[i] = g_sbuf[t & 1][i];
        __syncthreads();
        float z    = g_u0[r] + warpdot8(W_hh + (size_t)r * H, (const float4*)smemS);
        float snew = tanhf(z);
        if (lane == 0) {
            g_sbuf[(t + 1) & 1][r] = snew;
            sh_hp[warp]            = snew * __ldg(W_halt + r);
        }
        __syncthreads();
        if (tid == 0) {
            float hp = 0.f;
#pragma unroll
            for (int i = 0; i < RPB; i++) hp += sh_hp[i];
            g_hpart[(t + 1) & 1][bid] = hp;
        }
        t++;
        gbar();
    }

    if (haltstep >= 0) {
        // y = W_out @ s_halt + b_out ; s = s_halt  (W_out prefix pinned in L2)
        for (int i = tid; i < H; i += THREADS) smemS[i] = g_sbuf[haltstep & 1][i];
        __syncthreads();
        float yv = warpdot_out(W_out + (size_t)r * H, (const float4*)smemS) + b_out[r];
        if (lane == 0) {
            out[r]     = yv;
            out[H + r] = smemS[r];
        }
        if (bid == 0 && tid == 0) {
            out[2 * H]     = ponder;           // = haltstep = n-1
            out[2 * H + 1] = lastacc - 1.f;
        }
    } else {
        // never halted within 16 steps: halt_bin all zero
        int g = bid * THREADS + tid;
        if (g < H) { out[g] = 0.f; out[H + g] = 0.f; }
        if (g == 0) { out[2 * H] = ponder; out[2 * H + 1] = -1.f; }
    }
}

extern "C" void kernel_launch(void* const* d_in, const int* in_sizes, int n_in,
                              void* d_out, int out_size) {
    (void)in_sizes; (void)n_in; (void)out_size;
    // idempotent attribute set (not an allocation; safe pre-capture and in capture)
    cudaFuncSetAttribute(skiparnn_kernel,
                         cudaFuncAttributeMaxDynamicSharedMemorySize,
                         SMEM_FLOATS * (int)sizeof(float));
    skiparnn_kernel<<<GRID, THREADS, SMEM_FLOATS * sizeof(float)>>>(
        (const float*)d_in[0],  (const float*)d_in[1],
        (const float*)d_in[2],  (const float*)d_in[3],
        (const float*)d_in[4],  (const float*)d_in[5],
        (const float*)d_in[6],  (const float*)d_in[7],
        (const float*)d_in[8],  (const float*)d_in[9],
        (const float*)d_in[10], (const float*)d_in[11],
        (float*)d_out);
}

// round 11
// speedup vs baseline: 1.2262x; 1.0617x over previous
#include <cuda_runtime.h>
#include <math.h>

#define H 4096
#define GRID 256
#define THREADS 512
#define RPB 16           // rows per block (one per warp)
#define NMAX 16
#define THRESH 0.99f     // 1 - EPS

#define CK 256           // chunk: floats per row per stage
#define NCHUNK (H / CK)  // 16
#define DEPTH 2          // pipeline depth

#define PIN_IN_CHUNKS 6     // W_ih: first 6 of 16 chunks pinned -> 25.2 MB
#define PIN_OUT_BLKS 320    // W_out: first 320 of 512 8-float blocks pinned -> 41.9 MB
// total pinned = 67.1 MB == proven-safe evict_last capacity (R5)

// dynamic smem layout (floats): X[4096] | S[4096] | bufI[DEPTH*RPB*CK] | bufH[DEPTH*RPB*CK]
#define SMEM_FLOATS (2 * H + 2 * DEPTH * RPB * CK)

// ---- scratch (no allocations allowed) ----
__device__ float g_u0[H];          // W_ih@x0 + b_ih + b_hh (steps t>=1)
__device__ float g_sbuf[2][H];     // ping-pong hidden state
__device__ float g_hpart[2][GRID]; // per-block halt-dot partials (ping-pong)
__device__ unsigned g_barcount = 0;
__device__ unsigned g_bargen = 0;

// 256-bit pinned load: L2::evict_last
__device__ __forceinline__ void ldg256_keep(const float* __restrict__ p, float v[8]) {
    unsigned r0, r1, r2, r3, r4, r5, r6, r7;
    asm volatile("ld.global.nc.L2::evict_last.v8.b32 {%0,%1,%2,%3,%4,%5,%6,%7}, [%8];"
                 : "=r"(r0), "=r"(r1), "=r"(r2), "=r"(r3),
                   "=r"(r4), "=r"(r5), "=r"(r6), "=r"(r7)
                 : "l"(p));
    v[0] = __uint_as_float(r0); v[1] = __uint_as_float(r1);
    v[2] = __uint_as_float(r2); v[3] = __uint_as_float(r3);
    v[4] = __uint_as_float(r4); v[5] = __uint_as_float(r5);
    v[6] = __uint_as_float(r6); v[7] = __uint_as_float(r7);
}
// 256-bit streamed load: L2::evict_first
__device__ __forceinline__ void ldg256_stream(const float* __restrict__ p, float v[8]) {
    unsigned r0, r1, r2, r3, r4, r5, r6, r7;
    asm volatile("ld.global.nc.L2::evict_first.v8.b32 {%0,%1,%2,%3,%4,%5,%6,%7}, [%8];"
                 : "=r"(r0), "=r"(r1), "=r"(r2), "=r"(r3),
                   "=r"(r4), "=r"(r5), "=r"(r6), "=r"(r7)
                 : "l"(p));
    v[0] = __uint_as_float(r0); v[1] = __uint_as_float(r1);
    v[2] = __uint_as_float(r2); v[3] = __uint_as_float(r3);
    v[4] = __uint_as_float(r4); v[5] = __uint_as_float(r5);
    v[6] = __uint_as_float(r6); v[7] = __uint_as_float(r7);
}

// cp.async 16B with an L2 cache-hint policy
__device__ __forceinline__ void cp16(unsigned smem_addr, const float* __restrict__ g,
                                     unsigned long long pol) {
    asm volatile("cp.async.cg.shared.global.L2::cache_hint [%0], [%1], 16, %2;"
                 :: "r"(smem_addr), "l"(g), "l"(pol) : "memory");
}
__device__ __forceinline__ void cp_commit() {
    asm volatile("cp.async.commit_group;" ::: "memory");
}
template <int N>
__device__ __forceinline__ void cp_wait() {
    asm volatile("cp.async.wait_group %0;" :: "n"(N) : "memory");
}

// grid-wide barrier (all GRID blocks co-resident: 2 CTA/SM x 148 SM = 296 >= 256)
__device__ __forceinline__ void gbar() {
    __syncthreads();
    if (threadIdx.x == 0) {
        __threadfence();
        unsigned gen = *(volatile unsigned*)&g_bargen;
        if (atomicAdd(&g_barcount, 1u) == GRID - 1u) {
            g_barcount = 0u;
            __threadfence();
            atomicExch(&g_bargen, gen + 1u);
        } else {
            while (*(volatile unsigned*)&g_bargen == gen) { }
            __threadfence();
        }
    }
    __syncthreads();
}

// single-stream warp dot, evict-first LDG.128 (rare t>=1 path); result in ALL lanes
__device__ __forceinline__ float warpdot8(const float* __restrict__ w,
                                          const float4* __restrict__ sv) {
    const float4* wr = (const float4*)w;
    const int lane = threadIdx.x & 31;
    float acc = 0.f;
#pragma unroll 8
    for (int i = lane; i < H / 4; i += 32) {
        float4 a = __ldcs(wr + i);
        float4 b = sv[i];
        acc = fmaf(a.x, b.x, acc);
        acc = fmaf(a.y, b.y, acc);
        acc = fmaf(a.z, b.z, acc);
        acc = fmaf(a.w, b.w, acc);
    }
#pragma unroll
    for (int o = 16; o > 0; o >>= 1) acc += __shfl_xor_sync(0xffffffffu, acc, o);
    return acc;
}

__device__ __forceinline__ float fma8v(const float a[8], const float4* sv, int i, float acc) {
    float4 b0 = sv[2 * i];
    float4 b1 = sv[2 * i + 1];
    acc = fmaf(a[0], b0.x, acc);
    acc = fmaf(a[1], b0.y, acc);
    acc = fmaf(a[2], b0.z, acc);
    acc = fmaf(a[3], b0.w, acc);
    acc = fmaf(a[4], b1.x, acc);
    acc = fmaf(a[5], b1.y, acc);
    acc = fmaf(a[6], b1.z, acc);
    acc = fmaf(a[7], b1.w, acc);
    return acc;
}

// W_out warp dot: first PIN_OUT_BLKS blocks pinned (evict_last), rest streamed
__device__ __forceinline__ float warpdot_out(const float* __restrict__ w,
                                             const float4* __restrict__ sv) {
    const int lane = threadIdx.x & 31;
    float acc = 0.f;
#pragma unroll 4
    for (int i = lane; i < PIN_OUT_BLKS; i += 32) {
        float a[8];
        ldg256_keep(w + (size_t)i * 8, a);
        acc = fma8v(a, sv, i, acc);
    }
    for (int i = PIN_OUT_BLKS + lane; i < H / 8; i += 32) {
        float a[8];
        ldg256_stream(w + (size_t)i * 8, a);
        acc = fma8v(a, sv, i, acc);
    }
#pragma unroll
    for (int o = 16; o > 0; o >>= 1) acc += __shfl_xor_sync(0xffffffffu, acc, o);
    return acc;
}

__global__ void __launch_bounds__(THREADS, 2) skiparnn_kernel(
    const float* __restrict__ x,     const float* __restrict__ s0,
    const float* __restrict__ y0,    const float* __restrict__ h0,
    const float* __restrict__ W_ih,  const float* __restrict__ b_ih,
    const float* __restrict__ W_hh,  const float* __restrict__ b_hh,
    const float* __restrict__ W_halt,const float* __restrict__ b_halt,
    const float* __restrict__ W_out, const float* __restrict__ b_out,
    float* __restrict__ out)
{
    extern __shared__ __align__(16) float dyn[];
    float* smemX = dyn;                 // [H]
    float* smemS = dyn + H;             // [H]
    float* bufI  = dyn + 2 * H;                     // [DEPTH][RPB][CK]
    float* bufH  = dyn + 2 * H + DEPTH * RPB * CK;  // [DEPTH][RPB][CK]
    __shared__ float sh_hp[RPB];

    const int tid  = threadIdx.x;
    const int warp = tid >> 5;
    const int lane = tid & 31;
    const int bid  = blockIdx.x;
    const int r    = bid * RPB + warp;          // this warp's row (0..4095)

    const float h0v = h0[0];
    if (h0v >= THRESH) {
        int g = bid * THREADS + tid;
        if (g < H) { out[g] = y0[g]; out[H + g] = s0[g]; }
        if (g == 0) { out[2 * H] = 0.f; out[2 * H + 1] = h0v - 1.f; }
        return;
    }

    // ---- step 0: cp.async depth-2 pipelined dual matvec ----
    {
        unsigned long long polKeep, polStream;
        asm volatile("createpolicy.fractional.L2::evict_last.b64 %0, 1.0;" : "=l"(polKeep));
        asm volatile("createpolicy.fractional.L2::evict_first.b64 %0, 1.0;" : "=l"(polStream));

        const float* wi = W_ih + (size_t)r * H;
        const float* wh = W_hh + (size_t)r * H;
        unsigned bI = (unsigned)__cvta_generic_to_shared(bufI + warp * CK);
        unsigned bH = (unsigned)__cvta_generic_to_shared(bufH + warp * CK);
        const unsigned slotStride = RPB * CK * 4u;   // bytes per slot

        // prologue FIRST (doesn't need smemX/S): stages 0..DEPTH-1 in flight early
#pragma unroll
        for (int c = 0; c < DEPTH; c++) {
            int slot = c;
            unsigned long long pI = (c < PIN_IN_CHUNKS) ? polKeep : polStream;
#pragma unroll
            for (int k = 0; k < CK / 128; k++) {
                int j = k * 32 + lane;
                cp16(bI + slot * slotStride + j * 16u, wi + c * CK + j * 4, pI);
                cp16(bH + slot * slotStride + j * 16u, wh + c * CK + j * 4, polStream);
            }
            cp_commit();
        }

        // stage x1 and s0 into shared (overlaps with in-flight cp.async)
        for (int i = tid; i < H; i += THREADS) {
            smemX[i] = (i == 0) ? 1.f : x[i - 1];
            smemS[i] = s0[i];
        }
        __syncthreads();

        float accI = 0.f, accH = 0.f;
        const float4* sx4 = (const float4*)smemX;
        const float4* ss4 = (const float4*)smemS;
        const float4* bI4 = (const float4*)(bufI + warp * CK);
        const float4* bH4 = (const float4*)(bufH + warp * CK);
        const int slotStride4 = RPB * CK / 4;      // float4 per slot

        for (int c = 0; c < NCHUNK; c++) {
            cp_wait<DEPTH - 1>();                  // stage c complete (per-thread)
            int slot = c % DEPTH;
#pragma unroll
            for (int k = 0; k < CK / 128; k++) {
                int j = k * 32 + lane;             // float4 index within chunk
                float4 a  = bI4[slot * slotStride4 + j];
                float4 b  = bH4[slot * slotStride4 + j];
                float4 xv = sx4[c * (CK / 4) + j];
                float4 sv = ss4[c * (CK / 4) + j];
                accI = fmaf(a.x, xv.x, accI);
                accI = fmaf(a.y, xv.y, accI);
                accI = fmaf(a.z, xv.z, accI);
                accI = fmaf(a.w, xv.w, accI);
                accH = fmaf(b.x, sv.x, accH);
                accH = fmaf(b.y, sv.y, accH);
                accH = fmaf(b.z, sv.z, accH);
                accH = fmaf(b.w, sv.w, accH);
            }
            int cn = c + DEPTH;
            if (cn < NCHUNK) {
                int ns = cn % DEPTH;
                unsigned long long pI = (cn < PIN_IN_CHUNKS) ? polKeep : polStream;
#pragma unroll
                for (int k = 0; k < CK / 128; k++) {
                    int j = k * 32 + lane;
                    cp16(bI + ns * slotStride + j * 16u, wi + cn * CK + j * 4, pI);
                    cp16(bH + ns * slotStride + j * 16u, wh + cn * CK + j * 4, polStream);
                }
            }
            cp_commit();                           // keep group count advancing
        }
        cp_wait<0>();

#pragma unroll
        for (int o = 16; o > 0; o >>= 1) {
            accI += __shfl_xor_sync(0xffffffffu, accI, o);
            accH += __shfl_xor_sync(0xffffffffu, accH, o);
        }
        float bias = b_ih[r] + b_hh[r];
        float snew = tanhf(accI + bias + accH);
        if (lane == 0) {
            // W_ih@x0 = W_ih@x1 - W_ih[:,0]
            g_u0[r]      = accI - __ldg(W_ih + (size_t)r * H) + bias;
            g_sbuf[0][r] = snew;
            sh_hp[warp]  = snew * __ldg(W_halt + r);
        }
    }
    __syncthreads();
    if (tid == 0) {
        float hp = 0.f;
#pragma unroll
        for (int i = 0; i < RPB; i++) hp += sh_hp[i];
        g_hpart[0][bid] = hp;
    }
    gbar();

    float acc    = h0v;
    float ponder = 0.f;
    const float bh = b_halt[0];
    int   t = 0;
    int   haltstep = -1;
    float lastacc  = 0.f;

    while (true) {
        // unconditional copy of the current state into smemS — needed by BOTH the
        // halt path (W_out dot) and the continue path (W_hh dot). Issued before the
        // halt reduction so the two global-load streams overlap.
        for (int i = tid; i < H; i += THREADS) smemS[i] = g_sbuf[t & 1][i];

        // deterministic fixed-order reduction of halt-dot partials (same in all blocks)
        float hd;
        {
            const float* hp = g_hpart[t & 1];
            float a = 0.f;
#pragma unroll
            for (int i = lane; i < GRID; i += 32) a += hp[i];
#pragma unroll
            for (int o = 16; o > 0; o >>= 1) a += __shfl_xor_sync(0xffffffffu, a, o);
            hd = a;
        }
        float accNew = acc + 2.f / (1.f + expf(-(hd + bh)));
        __syncthreads();                            // smemS ready
        if (accNew >= THRESH) { haltstep = t; lastacc = accNew; break; }
        ponder += 1.f;
        acc = accNew;
        if (t == NMAX - 1) break;

        // ---- step t+1: z = u0 + W_hh @ s (streamed; rare path) ----
        float z    = g_u0[r] + warpdot8(W_hh + (size_t)r * H, (const float4*)smemS);
        float snew = tanhf(z);
        if (lane == 0) {
            g_sbuf[(t + 1) & 1][r] = snew;
            sh_hp[warp]            = snew * __ldg(W_halt + r);
        }
        __syncthreads();
        if (tid == 0) {
            float hp = 0.f;
#pragma unroll
            for (int i = 0; i < RPB; i++) hp += sh_hp[i];
            g_hpart[(t + 1) & 1][bid] = hp;
        }
        t++;
        gbar();
    }

    if (haltstep >= 0) {
        // y = W_out @ s_halt + b_out ; smemS already holds s_halt
        float yv = warpdot_out(W_out + (size_t)r * H, (const float4*)smemS) + b_out[r];
        if (lane == 0) {
            out[r]     = yv;
            out[H + r] = smemS[r];
        }
        if (bid == 0 && tid == 0) {
            out[2 * H]     = ponder;           // = haltstep = n-1
            out[2 * H + 1] = lastacc - 1.f;
        }
    } else {
        // never halted within 16 steps: halt_bin all zero
        int g = bid * THREADS + tid;
        if (g < H) { out[g] = 0.f; out[H + g] = 0.f; }
        if (g == 0) { out[2 * H] = ponder; out[2 * H + 1] = -1.f; }
    }
}

extern "C" void kernel_launch(void* const* d_in, const int* in_sizes, int n_in,
                              void* d_out, int out_size) {
    (void)in_sizes; (void)n_in; (void)out_size;
    // idempotent attribute set (not an allocation; safe pre-capture and in capture)
    cudaFuncSetAttribute(skiparnn_kernel,
                         cudaFuncAttributeMaxDynamicSharedMemorySize,
                         SMEM_FLOATS * (int)sizeof(float));
    skiparnn_kernel<<<GRID, THREADS, SMEM_FLOATS * sizeof(float)>>>(
        (const float*)d_in[0],  (const float*)d_in[1],
        (const float*)d_in[2],  (const float*)d_in[3],
        (const float*)d_in[4],  (const float*)d_in[5],
        (const float*)d_in[6],  (const float*)d_in[7],
        (const float*)d_in[8],  (const float*)d_in[9],
        (const float*)d_in[10], (const float*)d_in[11],
        (float*)d_out);
}

// round 12
// speedup vs baseline: 1.2974x; 1.0580x over previous
#include <cuda_runtime.h>
#include <math.h>

#define H 4096
#define GRID 256
#define THREADS 512
#define RPB 16           // rows per block (one per warp)
#define NMAX 16
#define THRESH 0.99f     // 1 - EPS

#define CK 256           // chunk: floats per row per stage
#define NCHUNK (H / CK)  // 16
#define DEPTH 2          // pipeline depth

#define PIN_IN_CHUNKS 8     // W_ih: first 8 of 16 chunks pinned -> 33.5 MB
#define PIN_OUT_BLKS 320    // W_out: first 320 of 512 8-float blocks pinned -> 41.9 MB
// total pinned = 75.4 MB — probing the retention bracket (67 MB ok, 84 MB broken)

// dynamic smem layout (floats): X[4096] | S[4096] | bufI[DEPTH*RPB*CK] | bufH[DEPTH*RPB*CK]
#define SMEM_FLOATS (2 * H + 2 * DEPTH * RPB * CK)

// ---- scratch (no allocations allowed) ----
__device__ float g_u0[H];          // W_ih@x0 + b_ih + b_hh (steps t>=1)
__device__ float g_sbuf[2][H];     // ping-pong hidden state
__device__ float g_hpart[2][GRID]; // per-block halt-dot partials (ping-pong)
__device__ unsigned g_barcount = 0;
__device__ unsigned g_bargen = 0;

// 256-bit pinned load: L2::evict_last
__device__ __forceinline__ void ldg256_keep(const float* __restrict__ p, float v[8]) {
    unsigned r0, r1, r2, r3, r4, r5, r6, r7;
    asm volatile("ld.global.nc.L2::evict_last.v8.b32 {%0,%1,%2,%3,%4,%5,%6,%7}, [%8];"
                 : "=r"(r0), "=r"(r1), "=r"(r2), "=r"(r3),
                   "=r"(r4), "=r"(r5), "=r"(r6), "=r"(r7)
                 : "l"(p));
    v[0] = __uint_as_float(r0); v[1] = __uint_as_float(r1);
    v[2] = __uint_as_float(r2); v[3] = __uint_as_float(r3);
    v[4] = __uint_as_float(r4); v[5] = __uint_as_float(r5);
    v[6] = __uint_as_float(r6); v[7] = __uint_as_float(r7);
}
// 256-bit streamed load: L2::evict_first
__device__ __forceinline__ void ldg256_stream(const float* __restrict__ p, float v[8]) {
    unsigned r0, r1, r2, r3, r4, r5, r6, r7;
    asm volatile("ld.global.nc.L2::evict_first.v8.b32 {%0,%1,%2,%3,%4,%5,%6,%7}, [%8];"
                 : "=r"(r0), "=r"(r1), "=r"(r2), "=r"(r3),
                   "=r"(r4), "=r"(r5), "=r"(r6), "=r"(r7)
                 : "l"(p));
    v[0] = __uint_as_float(r0); v[1] = __uint_as_float(r1);
    v[2] = __uint_as_float(r2); v[3] = __uint_as_float(r3);
    v[4] = __uint_as_float(r4); v[5] = __uint_as_float(r5);
    v[6] = __uint_as_float(r6); v[7] = __uint_as_float(r7);
}

// cp.async 16B with an L2 cache-hint policy
__device__ __forceinline__ void cp16(unsigned smem_addr, const float* __restrict__ g,
                                     unsigned long long pol) {
    asm volatile("cp.async.cg.shared.global.L2::cache_hint [%0], [%1], 16, %2;"
                 :: "r"(smem_addr), "l"(g), "l"(pol) : "memory");
}
__device__ __forceinline__ void cp_commit() {
    asm volatile("cp.async.commit_group;" ::: "memory");
}
template <int N>
__device__ __forceinline__ void cp_wait() {
    asm volatile("cp.async.wait_group %0;" :: "n"(N) : "memory");
}

// grid-wide barrier (all GRID blocks co-resident: 2 CTA/SM x 148 SM = 296 >= 256)
__device__ __forceinline__ void gbar() {
    __syncthreads();
    if (threadIdx.x == 0) {
        __threadfence();
        unsigned gen = *(volatile unsigned*)&g_bargen;
        if (atomicAdd(&g_barcount, 1u) == GRID - 1u) {
            g_barcount = 0u;
            __threadfence();
            atomicExch(&g_bargen, gen + 1u);
        } else {
            while (*(volatile unsigned*)&g_bargen == gen) { }
            __threadfence();
        }
    }
    __syncthreads();
}

// single-stream warp dot, evict-first LDG.128 (rare t>=1 path); result in ALL lanes
__device__ __forceinline__ float warpdot8(const float* __restrict__ w,
                                          const float4* __restrict__ sv) {
    const float4* wr = (const float4*)w;
    const int lane = threadIdx.x & 31;
    float acc = 0.f;
#pragma unroll 8
    for (int i = lane; i < H / 4; i += 32) {
        float4 a = __ldcs(wr + i);
        float4 b = sv[i];
        acc = fmaf(a.x, b.x, acc);
        acc = fmaf(a.y, b.y, acc);
        acc = fmaf(a.z, b.z, acc);
        acc = fmaf(a.w, b.w, acc);
    }
#pragma unroll
    for (int o = 16; o > 0; o >>= 1) acc += __shfl_xor_sync(0xffffffffu, acc, o);
    return acc;
}

__device__ __forceinline__ float fma8v(const float a[8], const float4* sv, int i, float acc) {
    float4 b0 = sv[2 * i];
    float4 b1 = sv[2 * i + 1];
    acc = fmaf(a[0], b0.x, acc);
    acc = fmaf(a[1], b0.y, acc);
    acc = fmaf(a[2], b0.z, acc);
    acc = fmaf(a[3], b0.w, acc);
    acc = fmaf(a[4], b1.x, acc);
    acc = fmaf(a[5], b1.y, acc);
    acc = fmaf(a[6], b1.z, acc);
    acc = fmaf(a[7], b1.w, acc);
    return acc;
}

// W_out warp dot: first PIN_OUT_BLKS blocks pinned (evict_last), rest streamed
__device__ __forceinline__ float warpdot_out(const float* __restrict__ w,
                                             const float4* __restrict__ sv) {
    const int lane = threadIdx.x & 31;
    float acc = 0.f;
#pragma unroll 4
    for (int i = lane; i < PIN_OUT_BLKS; i += 32) {
        float a[8];
        ldg256_keep(w + (size_t)i * 8, a);
        acc = fma8v(a, sv, i, acc);
    }
    for (int i = PIN_OUT_BLKS + lane; i < H / 8; i += 32) {
        float a[8];
        ldg256_stream(w + (size_t)i * 8, a);
        acc = fma8v(a, sv, i, acc);
    }
#pragma unroll
    for (int o = 16; o > 0; o >>= 1) acc += __shfl_xor_sync(0xffffffffu, acc, o);
    return acc;
}

__global__ void __launch_bounds__(THREADS, 2) skiparnn_kernel(
    const float* __restrict__ x,     const float* __restrict__ s0,
    const float* __restrict__ y0,    const float* __restrict__ h0,
    const float* __restrict__ W_ih,  const float* __restrict__ b_ih,
    const float* __restrict__ W_hh,  const float* __restrict__ b_hh,
    const float* __restrict__ W_halt,const float* __restrict__ b_halt,
    const float* __restrict__ W_out, const float* __restrict__ b_out,
    float* __restrict__ out)
{
    extern __shared__ __align__(16) float dyn[];
    float* smemX = dyn;                 // [H]
    float* smemS = dyn + H;             // [H]
    float* bufI  = dyn + 2 * H;                     // [DEPTH][RPB][CK]
    float* bufH  = dyn + 2 * H + DEPTH * RPB * CK;  // [DEPTH][RPB][CK]
    __shared__ float sh_hp[RPB];

    const int tid  = threadIdx.x;
    const int warp = tid >> 5;
    const int lane = tid & 31;
    const int bid  = blockIdx.x;
    const int r    = bid * RPB + warp;          // this warp's row (0..4095)

    const float h0v = h0[0];
    if (h0v >= THRESH) {
        int g = bid * THREADS + tid;
        if (g < H) { out[g] = y0[g]; out[H + g] = s0[g]; }
        if (g == 0) { out[2 * H] = 0.f; out[2 * H + 1] = h0v - 1.f; }
        return;
    }

    // ---- step 0: cp.async depth-2 pipelined dual matvec ----
    {
        unsigned long long polKeep, polStream;
        asm volatile("createpolicy.fractional.L2::evict_last.b64 %0, 1.0;" : "=l"(polKeep));
        asm volatile("createpolicy.fractional.L2::evict_first.b64 %0, 1.0;" : "=l"(polStream));

        const float* wi = W_ih + (size_t)r * H;
        const float* wh = W_hh + (size_t)r * H;
        unsigned bI = (unsigned)__cvta_generic_to_shared(bufI + warp * CK);
        unsigned bH = (unsigned)__cvta_generic_to_shared(bufH + warp * CK);
        const unsigned slotStride = RPB * CK * 4u;   // bytes per slot

        // prologue FIRST (doesn't need smemX/S): stages 0..DEPTH-1 in flight early
#pragma unroll
        for (int c = 0; c < DEPTH; c++) {
            int slot = c;
            unsigned long long pI = (c < PIN_IN_CHUNKS) ? polKeep : polStream;
#pragma unroll
            for (int k = 0; k < CK / 128; k++) {
                int j = k * 32 + lane;
                cp16(bI + slot * slotStride + j * 16u, wi + c * CK + j * 4, pI);
                cp16(bH + slot * slotStride + j * 16u, wh + c * CK + j * 4, polStream);
            }
            cp_commit();
        }

        // stage x1 and s0 into shared (overlaps with in-flight cp.async)
        for (int i = tid; i < H; i += THREADS) {
            smemX[i] = (i == 0) ? 1.f : x[i - 1];
            smemS[i] = s0[i];
        }
        __syncthreads();

        float accI = 0.f, accH = 0.f;
        const float4* sx4 = (const float4*)smemX;
        const float4* ss4 = (const float4*)smemS;
        const float4* bI4 = (const float4*)(bufI + warp * CK);
        const float4* bH4 = (const float4*)(bufH + warp * CK);
        const int slotStride4 = RPB * CK / 4;      // float4 per slot

        for (int c = 0; c < NCHUNK; c++) {
            cp_wait<DEPTH - 1>();                  // stage c complete (per-thread)
            int slot = c % DEPTH;
#pragma unroll
            for (int k = 0; k < CK / 128; k++) {
                int j = k * 32 + lane;             // float4 index within chunk
                float4 a  = bI4[slot * slotStride4 + j];
                float4 b  = bH4[slot * slotStride4 + j];
                float4 xv = sx4[c * (CK / 4) + j];
                float4 sv = ss4[c * (CK / 4) + j];
                accI = fmaf(a.x, xv.x, accI);
                accI = fmaf(a.y, xv.y, accI);
                accI = fmaf(a.z, xv.z, accI);
                accI = fmaf(a.w, xv.w, accI);
                accH = fmaf(b.x, sv.x, accH);
                accH = fmaf(b.y, sv.y, accH);
                accH = fmaf(b.z, sv.z, accH);
                accH = fmaf(b.w, sv.w, accH);
            }
            int cn = c + DEPTH;
            if (cn < NCHUNK) {
                int ns = cn % DEPTH;
                unsigned long long pI = (cn < PIN_IN_CHUNKS) ? polKeep : polStream;
#pragma unroll
                for (int k = 0; k < CK / 128; k++) {
                    int j = k * 32 + lane;
                    cp16(bI + ns * slotStride + j * 16u, wi + cn * CK + j * 4, pI);
                    cp16(bH + ns * slotStride + j * 16u, wh + cn * CK + j * 4, polStream);
                }
            }
            cp_commit();                           // keep group count advancing
        }
        cp_wait<0>();

#pragma unroll
        for (int o = 16; o > 0; o >>= 1) {
            accI += __shfl_xor_sync(0xffffffffu, accI, o);
            accH += __shfl_xor_sync(0xffffffffu, accH, o);
        }
        float bias = b_ih[r] + b_hh[r];
        float snew = tanhf(accI + bias + accH);
        if (lane == 0) {
            // W_ih@x0 = W_ih@x1 - W_ih[:,0]
            g_u0[r]      = accI - __ldg(W_ih + (size_t)r * H) + bias;
            g_sbuf[0][r] = snew;
            sh_hp[warp]  = snew * __ldg(W_halt + r);
        }
    }
    __syncthreads();
    if (tid == 0) {
        float hp = 0.f;
#pragma unroll
        for (int i = 0; i < RPB; i++) hp += sh_hp[i];
        g_hpart[0][bid] = hp;
    }
    gbar();

    float acc    = h0v;
    float ponder = 0.f;
    const float bh = b_halt[0];
    int   t = 0;
    int   haltstep = -1;
    float lastacc  = 0.f;

    while (true) {
        // unconditional copy of the current state into smemS — needed by BOTH paths
        for (int i = tid; i < H; i += THREADS) smemS[i] = g_sbuf[t & 1][i];

        // deterministic fixed-order reduction of halt-dot partials (same in all blocks)
        float hd;
        {
            const float* hp = g_hpart[t & 1];
            float a = 0.f;
#pragma unroll
            for (int i = lane; i < GRID; i += 32) a += hp[i];
#pragma unroll
            for (int o = 16; o > 0; o >>= 1) a += __shfl_xor_sync(0xffffffffu, a, o);
            hd = a;
        }
        float accNew = acc + 2.f / (1.f + expf(-(hd + bh)));
        __syncthreads();                            // smemS ready
        if (accNew >= THRESH) { haltstep = t; lastacc = accNew; break; }
        ponder += 1.f;
        acc = accNew;
        if (t == NMAX - 1) break;

        // ---- step t+1: z = u0 + W_hh @ s (streamed; rare path) ----
        float z    = g_u0[r] + warpdot8(W_hh + (size_t)r * H, (const float4*)smemS);
        float snew = tanhf(z);
        if (lane == 0) {
            g_sbuf[(t + 1) & 1][r] = snew;
            sh_hp[warp]            = snew * __ldg(W_halt + r);
        }
        __syncthreads();
        if (tid == 0) {
            float hp = 0.f;
#pragma unroll
            for (int i = 0; i < RPB; i++) hp += sh_hp[i];
            g_hpart[(t + 1) & 1][bid] = hp;
        }
        t++;
        gbar();
    }

    if (haltstep >= 0) {
        // y = W_out @ s_halt + b_out ; smemS already holds s_halt
        float yv = warpdot_out(W_out + (size_t)r * H, (const float4*)smemS) + b_out[r];
        if (lane == 0) {
            out[r]     = yv;
            out[H + r] = smemS[r];
        }
        if (bid == 0 && tid == 0) {
            out[2 * H]     = ponder;           // = haltstep = n-1
            out[2 * H + 1] = lastacc - 1.f;
        }
    } else {
        // never halted within 16 steps: halt_bin all zero
        int g = bid * THREADS + tid;
        if (g < H) { out[g] = 0.f; out[H + g] = 0.f; }
        if (g == 0) { out[2 * H] = ponder; out[2 * H + 1] = -1.f; }
    }
}

extern "C" void kernel_launch(void* const* d_in, const int* in_sizes, int n_in,
                              void* d_out, int out_size) {
    (void)in_sizes; (void)n_in; (void)out_size;
    // idempotent attribute set (not an allocation; safe pre-capture and in capture)
    cudaFuncSetAttribute(skiparnn_kernel,
                         cudaFuncAttributeMaxDynamicSharedMemorySize,
                         SMEM_FLOATS * (int)sizeof(float));
    skiparnn_kernel<<<GRID, THREADS, SMEM_FLOATS * sizeof(float)>>>(
        (const float*)d_in[0],  (const float*)d_in[1],
        (const float*)d_in[2],  (const float*)d_in[3],
        (const float*)d_in[4],  (const float*)d_in[5],
        (const float*)d_in[6],  (const float*)d_in[7],
        (const float*)d_in[8],  (const float*)d_in[9],
        (const float*)d_in[10], (const float*)d_in[11],
        (float*)d_out);
}